// round 8
// baseline (speedup 1.0000x reference)
#include <cuda_runtime.h>

// InteractionArch: out[b] = concat(dense[b] (128), sparse[b]·dense[b] (26),
//                                  triu_{k=1}(sparse[b]·sparse[b]^T) (325))
// B=16384, F=26, D=128, out stride 479 fp32 (row base only 4B-aligned).
//
// R8: dual-pipe operand delivery. 4x4 reg tiles (28 upper-tri tiles of the
// 7x7 grid), phase-aware lane->tile map so xi LDS.128 is 4 conflict-free
// phases (padded 36-float rows); xj comes from warp shuffles of register-
// resident per-lane vector chunks. Double-buffered cp.async k-chunks, FFMA2.

#define B_TOT 16384
#define NF 26
#define DD 128
#define NV 28
#define STRIDE 36          // padded floats per vector row (144 B)
#define CHUNK 32           // floats per k-chunk
#define CQ 8               // float4 quads per chunk
#define NCH 4              // chunks (128/32)
#define OUT_STRIDE 479

// phase-aware lane -> (ti, tj). Lanes 7,15,23,31 are pads (duplicate a tile,
// never store). Each 8-lane phase holds at most 2 ti-groups whose smem banks
// differ (16*ti mod 32), so xi loads are conflict-free.
__device__ __constant__ unsigned char c_TI[32] =
 {0,0,0,0,0,0,0,0,  1,1,1,1,1,1,6,1,  2,2,2,2,2,5,5,2,  3,3,3,3,4,4,4,3};
__device__ __constant__ unsigned char c_TJ[32] =
 {0,1,2,3,4,5,6,0,  1,2,3,4,5,6,6,1,  2,3,4,5,6,5,6,2,  3,4,5,6,4,5,6,3};

__device__ __forceinline__ void cp_async16(void* smem, const void* gmem) {
    unsigned s = (unsigned)__cvta_generic_to_shared(smem);
    asm volatile("cp.async.cg.shared.global [%0], [%1], 16;" :: "r"(s), "l"(gmem));
}
__device__ __forceinline__ void cp_commit() {
    asm volatile("cp.async.commit_group;");
}
template <int N>
__device__ __forceinline__ void cp_wait() {
    asm volatile("cp.async.wait_group %0;" :: "n"(N));
}
// packed f32x2 fma: acc(2xf32) += a(2xf32) * b(2xf32)
__device__ __forceinline__ void ffma2(unsigned long long& acc,
                                      unsigned long long a,
                                      unsigned long long b) {
    asm("fma.rn.f32x2 %0, %1, %2, %0;" : "+l"(acc) : "l"(a), "l"(b));
}

__global__ void __launch_bounds__(32, 16) interact_kernel(
    const float* __restrict__ dense,
    const float* __restrict__ sparse,
    float* __restrict__ out)
{
    __shared__ float Xs[2][NV][STRIDE];   // 8064 B

    const int lane = threadIdx.x;
    const int b    = blockIdx.x;

    // ---- dense passthrough to out[0:128] (scalar stores; base only 4B-aligned) ----
    {
        float4 dv = reinterpret_cast<const float4*>(dense + (size_t)b * DD)[lane];
        float* ob = out + (size_t)b * OUT_STRIDE;
        ob[4 * lane + 0] = dv.x;
        ob[4 * lane + 1] = dv.y;
        ob[4 * lane + 2] = dv.z;
        ob[4 * lane + 3] = dv.w;
    }

    const float* __restrict__ spb = sparse + (size_t)b * NF * DD;
    const float* __restrict__ dnb = dense + (size_t)b * DD;

    // ---- chunk loader (warp-cooperative): 26*8 sparse quads + 8 dense quads ----
    auto load_chunk = [&](int c, int buf) {
        #pragma unroll
        for (int t = 0; t < 7; t++) {
            int idx = lane + 32 * t;
            if (idx < NF * CQ) {
                int v = idx >> 3;
                int q = idx & 7;
                cp_async16(&Xs[buf][v][q * 4], spb + v * DD + c * CHUNK + q * 4);
            }
        }
        if (lane < CQ) {
            cp_async16(&Xs[buf][26][lane * 4], dnb + c * CHUNK + lane * 4);
        }
        cp_commit();
        // row 27 never written: its products are discarded in the epilogue.
    };

    const int ti = c_TI[lane];
    const int tj = c_TJ[lane];
    const bool active = ((lane & 7) != 7);     // pads never store
    const int vsrc = (lane < NV) ? lane : lane - 4;  // shuffle-source vector

    unsigned long long acc2[4][4];
    #pragma unroll
    for (int ii = 0; ii < 4; ii++)
        #pragma unroll
        for (int jj = 0; jj < 4; jj++)
            acc2[ii][jj] = 0ULL;

    // ---- pipelined chunk loop ----
    load_chunk(0, 0);
    #pragma unroll
    for (int c = 0; c < NCH; c++) {
        const int buf = c & 1;
        if (c + 1 < NCH) { load_chunk(c + 1, buf ^ 1); cp_wait<1>(); }
        else             { cp_wait<0>(); }
        __syncwarp();

        // stage own vector's chunk into registers (shuffle source)
        ulonglong2 ch[CQ];
        #pragma unroll
        for (int q = 0; q < CQ; q++)
            ch[q] = *reinterpret_cast<const ulonglong2*>(&Xs[buf][vsrc][q * 4]);

        #pragma unroll
        for (int kk = 0; kk < CQ; kk++) {
            // xi: smem, 4 conflict-free LDS.128
            ulonglong2 xi[4];
            #pragma unroll
            for (int ii = 0; ii < 4; ii++)
                xi[ii] = *reinterpret_cast<const ulonglong2*>(
                             &Xs[buf][4 * ti + ii][kk * 4]);
            // xj: warp shuffles from register-resident chunks
            ulonglong2 xj[4];
            #pragma unroll
            for (int jj = 0; jj < 4; jj++) {
                xj[jj].x = __shfl_sync(0xffffffffu, ch[kk].x, 4 * tj + jj);
                xj[jj].y = __shfl_sync(0xffffffffu, ch[kk].y, 4 * tj + jj);
            }
            #pragma unroll
            for (int ii = 0; ii < 4; ii++)
                #pragma unroll
                for (int jj = 0; jj < 4; jj++) {
                    ffma2(acc2[ii][jj], xi[ii].x, xj[jj].x);
                    ffma2(acc2[ii][jj], xi[ii].y, xj[jj].y);
                }
        }
        __syncwarp();   // all lanes done with buf before it is refilled
    }

    // ---- epilogue: horizontal add + scatter needed dots (i<j, j<=26) ----
    if (!active) return;
    float* ob = out + (size_t)b * OUT_STRIDE;
    #pragma unroll
    for (int ii = 0; ii < 4; ii++) {
        #pragma unroll
        for (int jj = 0; jj < 4; jj++) {
            const int i = 4 * ti + ii;
            const int j = 4 * tj + jj;
            if (i < j && j <= 26) {
                float2 p = *reinterpret_cast<float2*>(&acc2[ii][jj]);
                float v = p.x + p.y;
                int dst;
                if (j == 26) {
                    dst = 128 + i;                                        // sparse·dense
                } else {
                    dst = 154 + i * 25 - (i * (i - 1)) / 2 + (j - i - 1); // pair
                }
                ob[dst] = v;
            }
        }
    }
}

extern "C" void kernel_launch(void* const* d_in, const int* in_sizes, int n_in,
                              void* d_out, int out_size)
{
    (void)n_in; (void)out_size;
    const float* a = (const float*)d_in[0];
    const float* b = (const float*)d_in[1];
    // dense has B*D = 2,097,152 elems; sparse has B*F*D = 54,525,952 elems.
    const float* dense  = (in_sizes[0] < in_sizes[1]) ? a : b;
    const float* sparse = (in_sizes[0] < in_sizes[1]) ? b : a;

    interact_kernel<<<B_TOT, 32>>>(dense, sparse, (float*)d_out);
}